// round 3
// baseline (speedup 1.0000x reference)
#include <cuda_runtime.h>

#define HID 64
#define MAX_NODES 100000
#define MAX_EDGES 2000000
#define TE 96          // edges per block tile
#define SDT 100        // sDT row stride (floats): even (8B align), bank-friendly
#define EDGE_SMEM (64 * SDT * 4 + 64 * 64 * 8)   // sDT + splatted C

typedef unsigned long long ull;

// Scratch
__device__ float g_H[MAX_NODES * HID];
__device__ float g_P[MAX_NODES * HID];
__device__ float g_Q[MAX_NODES * HID];
__device__ int   g_U[MAX_EDGES];
__device__ int   g_V[MAX_EDGES];
__device__ int   g_is64;

// ---- packed f32x2 helpers (sm_103a FFMA2 path, PTX-only) --------------------
__device__ __forceinline__ ull pack2(float x, float y) {
    ull r; asm("mov.b64 %0, {%1, %2};" : "=l"(r) : "f"(x), "f"(y)); return r;
}
__device__ __forceinline__ void unpack2(ull v, float& x, float& y) {
    asm("mov.b64 {%0, %1}, %2;" : "=f"(x), "=f"(y) : "l"(v));
}
__device__ __forceinline__ ull ffma2(ull a, ull b, ull c) {
    ull r; asm("fma.rn.f32x2 %0, %1, %2, %3;" : "=l"(r) : "l"(a), "l"(b), "l"(c));
    return r;
}

// ---------------------------------------------------------------------------
// Kernel 0a: detect int64 vs int32 pairs (reads only first 2*n_edges words,
// in-bounds for both dtypes; int64 -> odd words all zero).
// ---------------------------------------------------------------------------
__global__ void detect_kernel(const int* __restrict__ w, int n_edges) {
    __shared__ int any_nz;
    if (threadIdx.x == 0) any_nz = 0;
    __syncthreads();
    int nz = 0;
    for (int j = threadIdx.x; j < 4096; j += blockDim.x) {
        long long idx = 1 + 2 * ((long long)j * (n_edges - 1) / 4096);
        if (idx < 2LL * n_edges) nz |= w[idx];
    }
    if (nz) atomicOr(&any_nz, 1);
    __syncthreads();
    if (threadIdx.x == 0) g_is64 = (any_nz == 0) ? 1 : 0;
}

__global__ void decode_kernel(const int* __restrict__ w, int n_edges) {
    int is64 = g_is64;
    int e = blockIdx.x * blockDim.x + threadIdx.x;
    if (e >= n_edges) return;
    int u, v;
    if (is64) { u = w[4LL * e]; v = w[4LL * e + 2]; }
    else      { u = w[2LL * e]; v = w[2LL * e + 1]; }
    g_U[e] = u;
    g_V[e] = v;
}

// ---------------------------------------------------------------------------
// Kernel 1: H = relu(relu(X@W1+b1)@W2+b2)
// 256 threads = 16 nodes x 16 dim-groups (cols 4q..4q+3, float4 LDS).
// ---------------------------------------------------------------------------
__global__ void node_mlp_kernel(const float* __restrict__ X,
                                const float* __restrict__ W1,
                                const float* __restrict__ b1,
                                const float* __restrict__ W2,
                                const float* __restrict__ b2,
                                int n_nodes) {
    __shared__ float sW1[4 * HID];
    __shared__ float sW2[HID * HID];
    __shared__ float sX[16][4];
    __shared__ float sh1[16][HID];

    int tid = threadIdx.x;
    for (int i = tid; i < HID * HID; i += 256) sW2[i] = W2[i];
    sW1[tid] = W1[tid];           // 256 == 4*HID
    __syncthreads();

    int q  = tid & 15;
    int nd = tid >> 4;
    float4 b1_4 = *(const float4*)&b1[4 * q];
    float4 b2_4 = *(const float4*)&b2[4 * q];

    for (int base = blockIdx.x * 16; base < n_nodes; base += gridDim.x * 16) {
        if (tid < 64) {
            int nl = tid >> 2, cc = tid & 3;
            int node = base + nl;
            sX[nl][cc] = (node < n_nodes) ? X[node * 4 + cc] : 0.f;
        }
        __syncthreads();

        int node = base + nd;
        float x0 = sX[nd][0], x1 = sX[nd][1], x2 = sX[nd][2], x3 = sX[nd][3];
        float4 w0 = *(const float4*)&sW1[0 * HID + 4 * q];
        float4 w1 = *(const float4*)&sW1[1 * HID + 4 * q];
        float4 w2 = *(const float4*)&sW1[2 * HID + 4 * q];
        float4 w3 = *(const float4*)&sW1[3 * HID + 4 * q];
        float h0 = fmaxf(fmaf(x3, w3.x, fmaf(x2, w2.x, fmaf(x1, w1.x, fmaf(x0, w0.x, b1_4.x)))), 0.f);
        float h1 = fmaxf(fmaf(x3, w3.y, fmaf(x2, w2.y, fmaf(x1, w1.y, fmaf(x0, w0.y, b1_4.y)))), 0.f);
        float h2 = fmaxf(fmaf(x3, w3.z, fmaf(x2, w2.z, fmaf(x1, w1.z, fmaf(x0, w0.z, b1_4.z)))), 0.f);
        float h3 = fmaxf(fmaf(x3, w3.w, fmaf(x2, w2.w, fmaf(x1, w1.w, fmaf(x0, w0.w, b1_4.w)))), 0.f);
        sh1[nd][4 * q + 0] = h0;
        sh1[nd][4 * q + 1] = h1;
        sh1[nd][4 * q + 2] = h2;
        sh1[nd][4 * q + 3] = h3;
        __syncthreads();

        if (node < n_nodes) {
            float4 a = b2_4;
            #pragma unroll 8
            for (int k = 0; k < HID; k++) {
                float h = sh1[nd][k];
                float4 w = *(const float4*)&sW2[k * HID + 4 * q];
                a.x = fmaf(h, w.x, a.x);
                a.y = fmaf(h, w.y, a.y);
                a.z = fmaf(h, w.z, a.z);
                a.w = fmaf(h, w.w, a.w);
            }
            a.x = fmaxf(a.x, 0.f); a.y = fmaxf(a.y, 0.f);
            a.z = fmaxf(a.z, 0.f); a.w = fmaxf(a.w, 0.f);
            *(float4*)&g_H[(size_t)node * HID + 4 * q] = a;
        }
        __syncthreads();
    }
}

// ---------------------------------------------------------------------------
// Kernel 2: P = H@A + be1 ; Q = H@B  (A = We1 rows 0..63, B = rows 64..127)
// Same 16x16 layout, float4 weight loads.
// ---------------------------------------------------------------------------
__global__ void node_pq_kernel(const float* __restrict__ We1,
                               const float* __restrict__ be1,
                               int n_nodes) {
    __shared__ float sA[HID * HID];
    __shared__ float sB[HID * HID];
    __shared__ float sh[16][HID];

    int tid = threadIdx.x;
    for (int i = tid; i < HID * HID; i += 256) {
        sA[i] = We1[i];
        sB[i] = We1[HID * HID + i];
    }
    __syncthreads();

    int q  = tid & 15;
    int nd = tid >> 4;
    float4 be4 = *(const float4*)&be1[4 * q];

    for (int base = blockIdx.x * 16; base < n_nodes; base += gridDim.x * 16) {
        int node = base + nd;
        bool valid = node < n_nodes;
        float4 h4 = valid ? *(const float4*)&g_H[(size_t)node * HID + 4 * q]
                          : make_float4(0.f, 0.f, 0.f, 0.f);
        *(float4*)&sh[nd][4 * q] = h4;
        __syncthreads();

        if (valid) {
            float4 p = be4;
            float4 qq = make_float4(0.f, 0.f, 0.f, 0.f);
            #pragma unroll 8
            for (int k = 0; k < HID; k++) {
                float h = sh[nd][k];
                float4 a4 = *(const float4*)&sA[k * HID + 4 * q];
                float4 b4 = *(const float4*)&sB[k * HID + 4 * q];
                p.x  = fmaf(h, a4.x, p.x);
                p.y  = fmaf(h, a4.y, p.y);
                p.z  = fmaf(h, a4.z, p.z);
                p.w  = fmaf(h, a4.w, p.w);
                qq.x = fmaf(h, b4.x, qq.x);
                qq.y = fmaf(h, b4.y, qq.y);
                qq.z = fmaf(h, b4.z, qq.z);
                qq.w = fmaf(h, b4.w, qq.w);
            }
            *(float4*)&g_P[(size_t)node * HID + 4 * q] = p;
            *(float4*)&g_Q[(size_t)node * HID + 4 * q] = qq;
        }
        __syncthreads();
    }
}

// ---------------------------------------------------------------------------
// Kernel 3 (persistent): per edge e=(u,v):
//   acc[t] = P[u][t] + Q[v][t] + sum_k |H[u][k]-H[v][k]| * C[k][t]
//   score  = sum_t relu(acc[t]) * We2[t] + be2
// 96-edge tiles. 256 thr = 16 tx (dims t=tx+16j) x 16 ty (6 edges = 3 pairs).
// Edge pairs packed into f32x2 lanes; mainloop is FFMA2.
// sDT[k][e] transposed diff tile (stride 100); sCs[k][t] = (C[k][t],C[k][t]).
// ---------------------------------------------------------------------------
__global__ void edge_kernel(const float* __restrict__ We1,
                            const float* __restrict__ We2,
                            const float* __restrict__ be2,
                            float* __restrict__ out,
                            int n_edges) {
    extern __shared__ char dynbuf[];
    float* sDT = (float*)dynbuf;                           // [64][SDT]
    ull*   sCs = (ull*)(dynbuf + 64 * SDT * 4);            // [64][64] splatted

    __shared__ int   su[TE], sv[TE];
    __shared__ float sW2v[HID];

    int tid = threadIdx.x;
    int tx  = tid & 15;
    int ty  = tid >> 4;

    // Build splatted C and We2 once (persistent)
    const float* C = We1 + 2 * HID * HID;
    for (int i = tid; i < HID * HID; i += 256) {
        float c = C[i];
        sCs[i] = pack2(c, c);
    }
    if (tid < HID) sW2v[tid] = We2[tid];
    float bias = be2[0];

    int n_tiles = (n_edges + TE - 1) / TE;

    for (int tile = blockIdx.x; tile < n_tiles; tile += gridDim.x) {
        int e0 = tile * TE;

        __syncthreads();   // protect su/sv/sDT from previous tile's readers
        if (tid < TE) {
            int e = e0 + tid;
            su[tid] = (e < n_edges) ? g_U[e] : 0;
            sv[tid] = (e < n_edges) ? g_V[e] : 0;
        }
        __syncthreads();

        // Fill transposed diff tile: j -> (k = j&63, edge-group eg = j>>6 of 4 edges)
        #pragma unroll
        for (int it = 0; it < 6; it++) {
            int j  = it * 256 + tid;
            int k  = j & 63;
            int eg = j >> 6;
            int u0 = su[4 * eg + 0], v0 = sv[4 * eg + 0];
            int u1 = su[4 * eg + 1], v1 = sv[4 * eg + 1];
            int u2 = su[4 * eg + 2], v2 = sv[4 * eg + 2];
            int u3 = su[4 * eg + 3], v3 = sv[4 * eg + 3];
            float d0 = fabsf(g_H[(size_t)u0 * HID + k] - g_H[(size_t)v0 * HID + k]);
            float d1 = fabsf(g_H[(size_t)u1 * HID + k] - g_H[(size_t)v1 * HID + k]);
            float d2 = fabsf(g_H[(size_t)u2 * HID + k] - g_H[(size_t)v2 * HID + k]);
            float d3 = fabsf(g_H[(size_t)u3 * HID + k] - g_H[(size_t)v3 * HID + k]);
            *(float4*)&sDT[k * SDT + 4 * eg] = make_float4(d0, d1, d2, d3);
        }

        // Init accumulators with P[u] + Q[v]; edges (6ty+2p, 6ty+2p+1) packed
        ull acc[3][4];
        #pragma unroll
        for (int p = 0; p < 3; p++) {
            int ea = 6 * ty + 2 * p;
            int ua = su[ea],     va = sv[ea];
            int ub = su[ea + 1], vb = sv[ea + 1];
            #pragma unroll
            for (int jj = 0; jj < 4; jj++) {
                int t = tx + 16 * jj;
                float xa = g_P[(size_t)ua * HID + t] + g_Q[(size_t)va * HID + t];
                float xb = g_P[(size_t)ub * HID + t] + g_Q[(size_t)vb * HID + t];
                acc[p][jj] = pack2(xa, xb);
            }
        }
        __syncthreads();   // sDT ready

        // FFMA2 mainloop
        const float* dbase = &sDT[6 * ty];
        const ull*   cbase = &sCs[tx];
        #pragma unroll 16
        for (int k = 0; k < HID; k++) {
            ull c0 = cbase[k * 64 + 0];
            ull c1 = cbase[k * 64 + 16];
            ull c2 = cbase[k * 64 + 32];
            ull c3 = cbase[k * 64 + 48];
            ull d0 = *(const ull*)&dbase[k * SDT + 0];
            ull d1 = *(const ull*)&dbase[k * SDT + 2];
            ull d2 = *(const ull*)&dbase[k * SDT + 4];
            acc[0][0] = ffma2(d0, c0, acc[0][0]);
            acc[0][1] = ffma2(d0, c1, acc[0][1]);
            acc[0][2] = ffma2(d0, c2, acc[0][2]);
            acc[0][3] = ffma2(d0, c3, acc[0][3]);
            acc[1][0] = ffma2(d1, c0, acc[1][0]);
            acc[1][1] = ffma2(d1, c1, acc[1][1]);
            acc[1][2] = ffma2(d1, c2, acc[1][2]);
            acc[1][3] = ffma2(d1, c3, acc[1][3]);
            acc[2][0] = ffma2(d2, c0, acc[2][0]);
            acc[2][1] = ffma2(d2, c1, acc[2][1]);
            acc[2][2] = ffma2(d2, c2, acc[2][2]);
            acc[2][3] = ffma2(d2, c3, acc[2][3]);
        }

        // Epilogue: relu, dot We2, reduce over 16 tx lanes
        float w0 = sW2v[tx], w1 = sW2v[tx + 16], w2 = sW2v[tx + 32], w3 = sW2v[tx + 48];
        #pragma unroll
        for (int p = 0; p < 3; p++) {
            float xa, xb, sa, sb;
            unpack2(acc[p][0], xa, xb);
            sa = fmaxf(xa, 0.f) * w0; sb = fmaxf(xb, 0.f) * w0;
            unpack2(acc[p][1], xa, xb);
            sa = fmaf(fmaxf(xa, 0.f), w1, sa); sb = fmaf(fmaxf(xb, 0.f), w1, sb);
            unpack2(acc[p][2], xa, xb);
            sa = fmaf(fmaxf(xa, 0.f), w2, sa); sb = fmaf(fmaxf(xb, 0.f), w2, sb);
            unpack2(acc[p][3], xa, xb);
            sa = fmaf(fmaxf(xa, 0.f), w3, sa); sb = fmaf(fmaxf(xb, 0.f), w3, sb);
            sa += __shfl_xor_sync(0xffffffffu, sa, 1);
            sa += __shfl_xor_sync(0xffffffffu, sa, 2);
            sa += __shfl_xor_sync(0xffffffffu, sa, 4);
            sa += __shfl_xor_sync(0xffffffffu, sa, 8);
            sb += __shfl_xor_sync(0xffffffffu, sb, 1);
            sb += __shfl_xor_sync(0xffffffffu, sb, 2);
            sb += __shfl_xor_sync(0xffffffffu, sb, 4);
            sb += __shfl_xor_sync(0xffffffffu, sb, 8);
            if (tx == 0) {
                int ea = e0 + 6 * ty + 2 * p;
                if (ea < n_edges)     out[ea]     = sa + bias;
                if (ea + 1 < n_edges) out[ea + 1] = sb + bias;
            }
        }
    }
}

// ---------------------------------------------------------------------------
extern "C" void kernel_launch(void* const* d_in, const int* in_sizes, int n_in,
                              void* d_out, int out_size) {
    const float* X     = (const float*)d_in[0];
    const int*   pairs = (const int*)d_in[1];
    const float* W1    = (const float*)d_in[2];
    const float* b1    = (const float*)d_in[3];
    const float* W2    = (const float*)d_in[4];
    const float* b2    = (const float*)d_in[5];
    const float* We1   = (const float*)d_in[6];
    const float* be1   = (const float*)d_in[7];
    const float* We2   = (const float*)d_in[8];
    const float* be2   = (const float*)d_in[9];
    float* out = (float*)d_out;

    int n_nodes = in_sizes[0] / 4;
    int n_edges = out_size;

    cudaFuncSetAttribute(edge_kernel,
                         cudaFuncAttributeMaxDynamicSharedMemorySize, EDGE_SMEM);

    detect_kernel<<<1, 256>>>(pairs, n_edges);
    decode_kernel<<<(n_edges + 255) / 256, 256>>>(pairs, n_edges);
    node_mlp_kernel<<<1024, 256>>>(X, W1, b1, W2, b2, n_nodes);
    node_pq_kernel<<<1024, 256>>>(We1, be1, n_nodes);
    edge_kernel<<<444, 256, EDGE_SMEM>>>(We1, We2, be2, out, n_edges);
}